// round 11
// baseline (speedup 1.0000x reference)
#include <cuda_runtime.h>
#include <cuda_bf16.h>
#include <cstdint>

// ChannelPruner: out[b,o,h,w] = sum_c w[o,c] * x[b,c,h,w]
// x: (32, 256, 56, 56) fp32; w: (256,256,1,1) fp32, sparse rows discovered at
// runtime (correct for ANY w).
//
// R11 = R10 (fused, 8192 one-plane blocks, MLP-4 LDG, smem-staged TMA bulk
// store) + explicit L2 retention policies:
//   - x loads:   ld.global.nc.L2::cache_hint with evict_last  (pin x in L2)
//   - out store: cp.async.bulk ... .L2::cache_hint with evict_first
// Across graph replays x (77MB hot set vs 126MB L2) becomes L2-resident and
// DRAM converges to a near-pure write stream.

#define N_CH        256
#define BATCH       32
#define HW4         784                   // (56*56)/4 float4 per plane
#define NPLANE      (BATCH * N_CH)        // 8192 blocks
#define PLANE_BYTES (HW4 * 16)            // 12544 B

__device__ __forceinline__ uint32_t smem_u32(const void* p) {
    uint32_t a;
    asm("{ .reg .u64 t; cvta.to.shared.u64 t, %1; cvt.u32.u64 %0, t; }"
        : "=r"(a) : "l"(p));
    return a;
}

__device__ __forceinline__ float4 ldg_evict_last(const float4* p, uint64_t pol) {
    float4 r;
    asm volatile("ld.global.nc.L2::cache_hint.v4.f32 {%0,%1,%2,%3}, [%4], %5;"
                 : "=f"(r.x), "=f"(r.y), "=f"(r.z), "=f"(r.w)
                 : "l"(p), "l"(pol));
    return r;
}

__global__ __launch_bounds__(256, 8) void prune_fused(const float4* __restrict__ x,
                                                      const float*  __restrict__ w,
                                                      float4* __restrict__ out) {
    __shared__ alignas(128) float4 s_out[HW4];   // 12544 B staging
    __shared__ int   s_cols[N_CH];
    __shared__ float s_vals[N_CH];
    __shared__ int   s_warp_off[9];

    const int tid  = threadIdx.x;
    const int lane = tid & 31;
    const int wid  = tid >> 5;

    const int bo = blockIdx.x;        // plane index b*256 + o
    const int o  = bo & (N_CH - 1);

    // L2 retention policies
    uint64_t pol_keep;   // for x reads: keep resident
    asm("createpolicy.fractional.L2::evict_last.b64 %0, 1.0;" : "=l"(pol_keep));
    uint64_t pol_stream; // for out writes: first victim
    asm("createpolicy.fractional.L2::evict_first.b64 %0, 1.0;" : "=l"(pol_stream));

    // ---- prologue: deterministic compaction of w row o (proven) ----
    const float wv = __ldg(&w[o * N_CH + tid]);
    const unsigned mask = __ballot_sync(0xffffffffu, wv != 0.0f);
    if (lane == 0) s_warp_off[wid + 1] = __popc(mask);
    __syncthreads();
    if (tid == 0) {
        int acc = 0;
        s_warp_off[0] = 0;
#pragma unroll
        for (int i = 0; i < 8; i++) { acc += s_warp_off[i + 1]; s_warp_off[i + 1] = acc; }
    }
    __syncthreads();
    if (wv != 0.0f) {
        const int pos = s_warp_off[wid] + __popc(mask & ((1u << lane) - 1u));
        s_cols[pos] = tid;
        s_vals[pos] = wv;
    }
    __syncthreads();

    const int nnz = s_warp_off[8];

    // ---- body: 4 float4 outputs per thread, MLP-4 LDG bursts ----
    float4 z = make_float4(0.f, 0.f, 0.f, 0.f);
    float4 a0 = z, a1 = z, a2 = z, a3 = z;

    const float4* xb = x + (size_t)(bo >> 8) * (N_CH * HW4);
    const bool tail = tid < (HW4 - 768);          // tid < 16

    for (int j = 0; j < nnz; j++) {
        const int   c = s_cols[j];
        const float v = s_vals[j];
        const float4* xc = xb + (size_t)c * HW4 + tid;
        const float4 r0 = ldg_evict_last(xc,       pol_keep);
        const float4 r1 = ldg_evict_last(xc + 256, pol_keep);
        const float4 r2 = ldg_evict_last(xc + 512, pol_keep);
        float4 r3 = z;
        if (tail) r3 = ldg_evict_last(xc + 768, pol_keep);

        a0.x += v * r0.x; a0.y += v * r0.y; a0.z += v * r0.z; a0.w += v * r0.w;
        a1.x += v * r1.x; a1.y += v * r1.y; a1.z += v * r1.z; a1.w += v * r1.w;
        a2.x += v * r2.x; a2.y += v * r2.y; a2.z += v * r2.z; a2.w += v * r2.w;
        if (tail) {
            a3.x += v * r3.x; a3.y += v * r3.y; a3.z += v * r3.z; a3.w += v * r3.w;
        }
    }

    // ---- epilogue: stage to smem, one TMA bulk store (evict_first) ----
    s_out[tid]       = a0;
    s_out[tid + 256] = a1;
    s_out[tid + 512] = a2;
    if (tail) s_out[tid + 768] = a3;
    __syncthreads();

    if (tid == 0) {
        asm volatile("fence.proxy.async.shared::cta;" ::: "memory");
        const uint32_t src = smem_u32(s_out);
        float4* dst = out + (size_t)bo * HW4;
        asm volatile(
            "cp.async.bulk.global.shared::cta.bulk_group.L2::cache_hint "
            "[%0], [%1], %2, %3;"
            :: "l"(dst), "r"(src), "r"((uint32_t)PLANE_BYTES), "l"(pol_stream)
            : "memory");
        asm volatile("cp.async.bulk.commit_group;" ::: "memory");
        asm volatile("cp.async.bulk.wait_group.read 0;" ::: "memory");
    }
}

extern "C" void kernel_launch(void* const* d_in, const int* in_sizes, int n_in,
                              void* d_out, int out_size) {
    const float4* x = (const float4*)d_in[0];
    const float*  w = (const float*)d_in[1];
    float4* out = (float4*)d_out;

    prune_fused<<<NPLANE, 256>>>(x, w, out);
}